// round 13
// baseline (speedup 1.0000x reference)
#include <cuda_runtime.h>

#define BATCH 8
#define NCH   6
#define HH    1024
#define WW    1024
#define TX    64
#define TY    64
#define HY    68      // halo rows: [by-2, by+66)
#define NPIX  (8.0f * 1024.0f * 1024.0f)
#define PIX_PER_B (HH * WW)          // 1<<20
#define CH_STRIDE4 (PIX_PER_B / 4)   // 262144

// Per-pixel 4-field moment word, written by classify:
//   m = cv | cv^2<<8 | tv<<16 | tv^2<<24   (cv,tv in [0,5])
// Horizontal 5-sums: 25/125/25/125 — no field carry.
__device__ unsigned g_mom[BATCH * PIX_PER_B];   // 32 MiB

// ---- Kernel A: streaming argmax + moment pack (4 pixels/thread) ----
__global__ __launch_bounds__(256) void dcl_classify(
    const float* __restrict__ pred, const void* __restrict__ tgt,
    float* __restrict__ out)
{
    // Targets in [0,5]; little-endian int64 => odd 32-bit words of the first
    // 64 elements all zero. P(false positive for int32) = (1/6)^32 ~ 0.
    const int lane = threadIdx.x & 31;
    const int probe = ((const int*)tgt)[2 * lane + 1];
    const int is64 = (__ballot_sync(0xffffffffu, probe != 0) == 0u);

    const unsigned t = blockIdx.x * 256u + threadIdx.x;     // pixel4 index
    if (t == 0) *out = 0.0f;
    const unsigned b   = t >> 18;
    const unsigned off = t & 0x3FFFFu;

    const float4* pp = (const float4*)pred + (size_t)b * NCH * CH_STRIDE4 + off;
    float4 v[NCH];
    #pragma unroll
    for (int ch = 0; ch < NCH; ++ch) v[ch] = pp[(size_t)ch * CH_STRIDE4];

    int t0, t1, t2, t3;
    if (is64) {
        const int4* tp = (const int4*)tgt + (size_t)t * 2;
        const int4 q0 = tp[0], q1 = tp[1];
        t0 = q0.x; t1 = q0.z; t2 = q1.x; t3 = q1.z;
    } else {
        const int4 q = ((const int4*)tgt)[t];
        t0 = q.x; t1 = q.y; t2 = q.z; t3 = q.w;
    }

    int i0 = 0, i1 = 0, i2 = 0, i3 = 0;
    float m0 = v[0].x, m1 = v[0].y, m2 = v[0].z, m3 = v[0].w;
    #pragma unroll
    for (int ch = 1; ch < NCH; ++ch) {
        if (v[ch].x > m0) { m0 = v[ch].x; i0 = ch; }
        if (v[ch].y > m1) { m1 = v[ch].y; i1 = ch; }
        if (v[ch].z > m2) { m2 = v[ch].z; i2 = ch; }
        if (v[ch].w > m3) { m3 = v[ch].w; i3 = ch; }
    }

    // moment(cv,tv) = cv*(cv<<8 | 1) + (tv*(tv<<8 | 1))<<16
    uint4 o;
    o.x = (unsigned)i0 * (((unsigned)i0 << 8) + 1u) + (((unsigned)t0 * (((unsigned)t0 << 8) + 1u)) << 16);
    o.y = (unsigned)i1 * (((unsigned)i1 << 8) + 1u) + (((unsigned)t1 * (((unsigned)t1 << 8) + 1u)) << 16);
    o.z = (unsigned)i2 * (((unsigned)i2 << 8) + 1u) + (((unsigned)t2 * (((unsigned)t2 << 8) + 1u)) << 16);
    o.w = (unsigned)i3 * (((unsigned)i3 << 8) + 1u) + (((unsigned)t3 * (((unsigned)t3 << 8) + 1u)) << 16);
    *(uint4*)&g_mom[t * 4u] = o;
}

// ---- Kernel B: adds-only stencil + MSE reduce ----
__global__ __launch_bounds__(512) void dcl_stencil(float* __restrict__ out)
{
    __shared__ unsigned hbuf[HY][TX];   // 17.4 KB: packed horizontal 5-sums

    const int tid = threadIdx.x;
    const int bx  = blockIdx.x * TX;
    const int by  = blockIdx.y * TY;
    const unsigned base_p = ((unsigned)blockIdx.z << 20);   // pixel base of batch

    // ---- Phase A: horizontal 5-sums (pure loads + adds) ----
    for (int i = tid; i < HY * (TX / 4); i += 512) {
        const int rr = i >> 4;              // halo row 0..67
        const int cw = i & 15;              // 4-px group within tile
        const int gy = by + rr - 2;
        uint2 L = make_uint2(0, 0), R = make_uint2(0, 0);
        uint4 B = make_uint4(0, 0, 0, 0);
        if ((unsigned)gy < (unsigned)HH) {
            const int gxc = bx + cw * 4;    // multiple of 4
            const unsigned p = base_p + ((unsigned)gy << 10) + (unsigned)gxc;
            B = *(const uint4*)&g_mom[p];                    // cols gxc..gxc+3
            if (gxc > 0)    L = *(const uint2*)&g_mom[p - 2];   // gxc-2, gxc-1
            if (gxc < 1020) R = *(const uint2*)&g_mom[p + 4];   // gxc+4, gxc+5
        }
        unsigned s = L.x + L.y + B.x + B.y + B.z;
        uint4 o;
        o.x = s; s += B.w - L.x;
        o.y = s; s += R.x - L.y;
        o.z = s; s += R.y - B.x;
        o.w = s;
        *(uint4*)&hbuf[rr][cw * 4] = o;
    }
    __syncthreads();

    // ---- Phase B: vertical sliding 5-window, 1 col x 8 rows per thread ----
    // Split each h-word into lo = s1c|s1t<<16 and hi = s2c|s2t<<16 (16-bit
    // fields; vertical 5-sums reach 125 / 625 — no carry).
    const int c  = tid & 63;
    const int r0 = (tid >> 6) * 8;

    unsigned lo[12], hi[12];
    #pragma unroll
    for (int d = 0; d < 12; ++d) {
        const unsigned w = hbuf[r0 + d][c];
        lo[d] = w & 0x00FF00FFu;
        hi[d] = (w >> 8) & 0x00FF00FFu;
    }
    unsigned sa = lo[0] + lo[1] + lo[2] + lo[3] + lo[4];
    unsigned sb = hi[0] + hi[1] + hi[2] + hi[3] + hi[4];

    int   acc_i = 0;
    float acc_s = 0.0f;
    #pragma unroll
    for (int rr = 0; rr < 8; ++rr) {
        // q = 25*sb evaluates both 25*s2 fields at once (25*625=15625 < 2^16).
        const unsigned q = sb * 25u;
        const int s1c = (int)(sa & 0xFFFFu), s1t = (int)(sa >> 16);
        const int np = (int)(q & 0xFFFFu) - s1c * s1c;   // exact, [0,15625]
        const int nt = (int)(q >> 16)     - s1t * s1t;
        acc_i += np + nt;
        // (sqrt(np/600)-sqrt(nt/600))^2 = (np + nt - 2*sqrt(np*nt))/600
        const float p = (float)(np * nt);
        float s;
        asm("sqrt.approx.f32 %0, %1;" : "=f"(s) : "f"(p));
        acc_s += s;
        if (rr < 7) { sa += lo[rr + 5] - lo[rr]; sb += hi[rr + 5] - hi[rr]; }
    }

    float acc = fmaf(-2.0f, acc_s, (float)acc_i) * (1.0f / (600.0f * NPIX));

    // ---- Reduce: warp shuffle -> smem -> one atomic per block ----
    #pragma unroll
    for (int o = 16; o > 0; o >>= 1)
        acc += __shfl_down_sync(0xffffffffu, acc, o);

    __shared__ float warpsum[16];
    if ((tid & 31) == 0) warpsum[tid >> 5] = acc;
    __syncthreads();
    if (tid < 16) {
        float v = warpsum[tid];
        #pragma unroll
        for (int o = 8; o > 0; o >>= 1)
            v += __shfl_down_sync(0xffffu, v, o);
        if (tid == 0) atomicAdd(out, v);
    }
}

extern "C" void kernel_launch(void* const* d_in, const int* in_sizes, int n_in,
                              void* d_out, int out_size) {
    const float* pred = (const float*)d_in[0];
    const void*  tgt  = d_in[1];
    float* out = (float*)d_out;

    const int n_p4_blocks = (BATCH * PIX_PER_B / 4) / 256;   // 8192
    dcl_classify<<<n_p4_blocks, 256>>>(pred, tgt, out);

    dim3 grid(WW / TX, HH / TY, BATCH);
    dcl_stencil<<<grid, 512>>>(out);
}

// round 14
// speedup vs baseline: 1.0722x; 1.0722x over previous
#include <cuda_runtime.h>

#define BATCH 8
#define NCH   6
#define HH    1024
#define WW    1024
#define TY    28          // nominal output rows per block
#define NYT   37          // y-tiles per image (36*28 + 16)
#define NBLOCKS (NYT * BATCH)
#define NPIX  (8.0f * 1024.0f * 1024.0f)
#define PIX_PER_B (HH * WW)
#define CH_STRIDE4 (PIX_PER_B / 4)
#define RAWW  (WW + 8)    // 4 pad cols each side

__device__ float g_partial;
__device__ int   g_done;

__device__ __forceinline__ unsigned fld_lo(unsigned w) { return w & 0x00FF00FFu; }
__device__ __forceinline__ unsigned fld_hi(unsigned w) { return (w >> 8) & 0x00FF00FFu; }

// Single-pass kernel: 296 blocks x 512 threads, all co-resident, independent.
// Each block handles a full-width row band [by, by+rows_out) of one batch:
// row-streaming pipeline (2 rows/step): classify -> raw moments (smem) ->
// horizontal 5-sums (8-row circular smem) -> vertical sliding window (regs).
// Moment word per pixel: cv | cv^2<<8 | tv<<16 | tv^2<<24 (cv,tv in [0,5]);
// horizontal 5-sums: 25/125/25/125 per field (no carry); vertical sums split
// into 16-bit-field accumulators (<=125 / <=625).
__global__ __launch_bounds__(512) void dcl_onepass(
    const float* __restrict__ pred, const void* __restrict__ tgt,
    float* __restrict__ out)
{
    __shared__ unsigned hbuf[8][WW];     // 32 KB circular horizontal-sum rows
    __shared__ unsigned raw[2][RAWW];    // 8.1 KB moment rows (+4 pad/side)
    __shared__ float    warpsum[16];

    const int tid      = threadIdx.x;
    const int by       = blockIdx.x * TY;
    const int batch    = blockIdx.y;
    const int rows_out = min(TY, HH - by);
    const int S_last   = rows_out / 2 + 1;       // steps s = 0..S_last

    // Targets in [0,5]; little-endian int64 => odd 32-bit words of the first
    // 64 elements all zero. P(false positive for int32) = (1/6)^32 ~ 0.
    const int lane  = tid & 31;
    const int probe = ((const int*)tgt)[2 * lane + 1];
    const int is64  = (__ballot_sync(0xffffffffu, probe != 0) == 0u);

    const float*     pbase = pred + (size_t)batch * NCH * PIX_PER_B;
    const long long* tb64  = (const long long*)tgt + (size_t)batch * PIX_PER_B;
    const int*       tb32  = (const int*)tgt       + (size_t)batch * PIX_PER_B;

    // Zero the pad columns of raw (written once, never overwritten).
    if (tid < 16) {
        const int rr = tid >> 3, j = tid & 7;
        raw[rr][j < 4 ? j : WW + j] = 0u;   // idx 0..3 and 1028..1031
    }

    const int srow = tid >> 8;          // 0..1: row within step
    const int cg   = (tid & 255) * 4;   // column base of this thread's group
    const int c0   = tid * 2;           // vertical: 2 fixed columns

    unsigned sa0 = 0, sb0 = 0, sa1 = 0, sb1 = 0;   // vertical window state
    int   acc_i = 0;
    float acc_s = 0.0f;

    for (int s = 0; s <= S_last; ++s) {
        // ---- classify 2 rows: argmax + moment pack ----
        const int gy = by - 2 + 2 * s + srow;
        uint4 mom = make_uint4(0, 0, 0, 0);
        if ((unsigned)gy < (unsigned)HH) {
            const float4* pp = (const float4*)(pbase + (size_t)gy * WW) + (cg >> 2);
            float4 v[NCH];
            #pragma unroll
            for (int ch = 0; ch < NCH; ++ch) v[ch] = pp[(size_t)ch * CH_STRIDE4];

            int t0, t1, t2, t3;
            if (is64) {
                const int4* tp = (const int4*)(tb64 + (size_t)gy * WW + cg);
                const int4 q0 = tp[0], q1 = tp[1];
                t0 = q0.x; t1 = q0.z; t2 = q1.x; t3 = q1.z;
            } else {
                const int4 q = *(const int4*)(tb32 + (size_t)gy * WW + cg);
                t0 = q.x; t1 = q.y; t2 = q.z; t3 = q.w;
            }

            int i0 = 0, i1 = 0, i2 = 0, i3 = 0;
            float m0 = v[0].x, m1 = v[0].y, m2 = v[0].z, m3 = v[0].w;
            #pragma unroll
            for (int ch = 1; ch < NCH; ++ch) {
                if (v[ch].x > m0) { m0 = v[ch].x; i0 = ch; }
                if (v[ch].y > m1) { m1 = v[ch].y; i1 = ch; }
                if (v[ch].z > m2) { m2 = v[ch].z; i2 = ch; }
                if (v[ch].w > m3) { m3 = v[ch].w; i3 = ch; }
            }
            mom.x = (unsigned)i0 * (((unsigned)i0 << 8) + 1u) + (((unsigned)t0 * (((unsigned)t0 << 8) + 1u)) << 16);
            mom.y = (unsigned)i1 * (((unsigned)i1 << 8) + 1u) + (((unsigned)t1 * (((unsigned)t1 << 8) + 1u)) << 16);
            mom.z = (unsigned)i2 * (((unsigned)i2 << 8) + 1u) + (((unsigned)t2 * (((unsigned)t2 << 8) + 1u)) << 16);
            mom.w = (unsigned)i3 * (((unsigned)i3 << 8) + 1u) + (((unsigned)t3 * (((unsigned)t3 << 8) + 1u)) << 16);
        }
        *(uint4*)&raw[srow][4 + cg] = mom;
        __syncthreads();

        // ---- horizontal 5-sums for the 2 new rows ----
        {
            const uint4 A = *(const uint4*)&raw[srow][cg];       // cols cg-4..cg-1
            const uint4 B = *(const uint4*)&raw[srow][cg + 4];   // cols cg..cg+3
            const uint4 C = *(const uint4*)&raw[srow][cg + 8];   // cols cg+4..cg+7
            unsigned ss = A.z + A.w + B.x + B.y + B.z;
            uint4 o;
            o.x = ss; ss += B.w - A.z;
            o.y = ss; ss += C.x - A.w;
            o.z = ss; ss += C.y - B.x;
            o.w = ss;
            *(uint4*)&hbuf[(2 * s + srow) & 7][cg] = o;
        }
        __syncthreads();

        // ---- vertical sliding window: 2 output rows, 2 cols/thread ----
        if (s >= 2) {
            if (s == 2) {
                #pragma unroll
                for (int d = 0; d < 5; ++d) {
                    const uint2 w = *(const uint2*)&hbuf[d][c0];
                    sa0 += fld_lo(w.x); sb0 += fld_hi(w.x);
                    sa1 += fld_lo(w.y); sb1 += fld_hi(w.y);
                }
            } else {
                const uint2 nw = *(const uint2*)&hbuf[(2 * s) & 7][c0];
                const uint2 ow = *(const uint2*)&hbuf[(2 * s - 5) & 7][c0];
                sa0 += fld_lo(nw.x) - fld_lo(ow.x); sb0 += fld_hi(nw.x) - fld_hi(ow.x);
                sa1 += fld_lo(nw.y) - fld_lo(ow.y); sb1 += fld_hi(nw.y) - fld_hi(ow.y);
            }
            #pragma unroll
            for (int half = 0; half < 2; ++half) {
                // emit both columns
                {
                    const unsigned q = sb0 * 25u;
                    const int s1c = (int)(sa0 & 0xFFFFu), s1t = (int)(sa0 >> 16);
                    const int np = (int)(q & 0xFFFFu) - s1c * s1c;
                    const int nt = (int)(q >> 16)     - s1t * s1t;
                    acc_i += np + nt;
                    const float p = (float)(np * nt);
                    float sq;
                    asm("sqrt.approx.f32 %0, %1;" : "=f"(sq) : "f"(p));
                    acc_s += sq;
                }
                {
                    const unsigned q = sb1 * 25u;
                    const int s1c = (int)(sa1 & 0xFFFFu), s1t = (int)(sa1 >> 16);
                    const int np = (int)(q & 0xFFFFu) - s1c * s1c;
                    const int nt = (int)(q >> 16)     - s1t * s1t;
                    acc_i += np + nt;
                    const float p = (float)(np * nt);
                    float sq;
                    asm("sqrt.approx.f32 %0, %1;" : "=f"(sq) : "f"(p));
                    acc_s += sq;
                }
                if (half == 0) {   // slide to second output row of this step
                    const uint2 nw = *(const uint2*)&hbuf[(2 * s + 1) & 7][c0];
                    const uint2 ow = *(const uint2*)&hbuf[(2 * s - 4) & 7][c0];
                    sa0 += fld_lo(nw.x) - fld_lo(ow.x); sb0 += fld_hi(nw.x) - fld_hi(ow.x);
                    sa1 += fld_lo(nw.y) - fld_lo(ow.y); sb1 += fld_hi(nw.y) - fld_hi(ow.y);
                }
            }
        }
    }

    // ---- Reduce: warp shuffle -> smem -> one atomic per block ----
    float acc = fmaf(-2.0f, acc_s, (float)acc_i) * (1.0f / (600.0f * NPIX));
    #pragma unroll
    for (int o = 16; o > 0; o >>= 1)
        acc += __shfl_down_sync(0xffffffffu, acc, o);

    if ((tid & 31) == 0) warpsum[tid >> 5] = acc;
    __syncthreads();
    if (tid < 16) {
        float v = warpsum[tid];
        #pragma unroll
        for (int o = 8; o > 0; o >>= 1)
            v += __shfl_down_sync(0xffffu, v, o);
        if (tid == 0) {
            atomicAdd(&g_partial, v);
            __threadfence();
            const int old = atomicAdd(&g_done, 1);
            if (old == NBLOCKS - 1) {
                // Last block: publish and reset for the next graph replay.
                *out = atomicAdd(&g_partial, 0.0f);
                g_partial = 0.0f;
                g_done = 0;
                __threadfence();
            }
        }
    }
}

extern "C" void kernel_launch(void* const* d_in, const int* in_sizes, int n_in,
                              void* d_out, int out_size) {
    const float* pred = (const float*)d_in[0];
    const void*  tgt  = d_in[1];
    float* out = (float*)d_out;

    dim3 grid(NYT, BATCH);
    dcl_onepass<<<grid, 512>>>(pred, tgt, out);
}

// round 15
// speedup vs baseline: 1.2952x; 1.2080x over previous
#include <cuda_runtime.h>

#define BATCH 8
#define NCH   6
#define HH    1024
#define WW    1024
#define TY    18          // nominal output rows per block
#define NYT   57          // y-tiles per image (56*18 + 16)
#define NBLOCKS (NYT * BATCH)
#define NPIX  (8.0f * 1024.0f * 1024.0f)
#define PIX_PER_B (HH * WW)
#define CH_STRIDE4 (PIX_PER_B / 4)
#define RAWW  (WW + 8)    // 4 pad cols each side

__device__ float g_partial;
__device__ int   g_done;

__device__ __forceinline__ unsigned fld_lo(unsigned w) { return w & 0x00FF00FFu; }
__device__ __forceinline__ unsigned fld_hi(unsigned w) { return (w >> 8) & 0x00FF00FFu; }

// Single-pass kernel: 456 blocks x 512 threads, ~3 blocks/SM so barrier stalls
// in one block are hidden by the other resident blocks' memory streams.
// Each block handles a full-width row band [by, by+rows_out) of one batch:
// row-streaming pipeline (2 rows/step): classify -> raw moments (smem) ->
// horizontal 5-sums (8-row circular smem) -> vertical sliding window (regs).
// Moment word per pixel: cv | cv^2<<8 | tv<<16 | tv^2<<24 (cv,tv in [0,5]);
// horizontal 5-sums: 25/125/25/125 per field (no carry); vertical sums split
// into 16-bit-field accumulators (<=125 / <=625).
__global__ __launch_bounds__(512, 3) void dcl_onepass(
    const float* __restrict__ pred, const void* __restrict__ tgt,
    float* __restrict__ out)
{
    __shared__ unsigned hbuf[8][WW];     // 32 KB circular horizontal-sum rows
    __shared__ unsigned raw[2][RAWW];    // 8.1 KB moment rows (+4 pad/side)
    __shared__ float    warpsum[16];

    const int tid      = threadIdx.x;
    const int by       = blockIdx.x * TY;
    const int batch    = blockIdx.y;
    const int rows_out = min(TY, HH - by);
    const int S_last   = rows_out / 2 + 1;       // steps s = 0..S_last (rows_out even)

    // Targets in [0,5]; little-endian int64 => odd 32-bit words of the first
    // 64 elements all zero. P(false positive for int32) = (1/6)^32 ~ 0.
    const int lane  = tid & 31;
    const int probe = ((const int*)tgt)[2 * lane + 1];
    const int is64  = (__ballot_sync(0xffffffffu, probe != 0) == 0u);

    const float*     pbase = pred + (size_t)batch * NCH * PIX_PER_B;
    const long long* tb64  = (const long long*)tgt + (size_t)batch * PIX_PER_B;
    const int*       tb32  = (const int*)tgt       + (size_t)batch * PIX_PER_B;

    // Zero the pad columns of raw (written once, never overwritten).
    if (tid < 16) {
        const int rr = tid >> 3, j = tid & 7;
        raw[rr][j < 4 ? j : WW + j] = 0u;   // idx 0..3 and 1028..1031
    }

    const int srow = tid >> 8;          // 0..1: row within step
    const int cg   = (tid & 255) * 4;   // column base of this thread's group
    const int c0   = tid * 2;           // vertical: 2 fixed columns

    unsigned sa0 = 0, sb0 = 0, sa1 = 0, sb1 = 0;   // vertical window state
    int   acc_i = 0;
    float acc_s = 0.0f;

    for (int s = 0; s <= S_last; ++s) {
        // ---- classify 2 rows: argmax + moment pack ----
        const int gy = by - 2 + 2 * s + srow;
        uint4 mom = make_uint4(0, 0, 0, 0);
        if ((unsigned)gy < (unsigned)HH) {
            const float4* pp = (const float4*)(pbase + (size_t)gy * WW) + (cg >> 2);
            float4 v[NCH];
            #pragma unroll
            for (int ch = 0; ch < NCH; ++ch) v[ch] = pp[(size_t)ch * CH_STRIDE4];

            int t0, t1, t2, t3;
            if (is64) {
                const int4* tp = (const int4*)(tb64 + (size_t)gy * WW + cg);
                const int4 q0 = tp[0], q1 = tp[1];
                t0 = q0.x; t1 = q0.z; t2 = q1.x; t3 = q1.z;
            } else {
                const int4 q = *(const int4*)(tb32 + (size_t)gy * WW + cg);
                t0 = q.x; t1 = q.y; t2 = q.z; t3 = q.w;
            }

            int i0 = 0, i1 = 0, i2 = 0, i3 = 0;
            float m0 = v[0].x, m1 = v[0].y, m2 = v[0].z, m3 = v[0].w;
            #pragma unroll
            for (int ch = 1; ch < NCH; ++ch) {
                if (v[ch].x > m0) { m0 = v[ch].x; i0 = ch; }
                if (v[ch].y > m1) { m1 = v[ch].y; i1 = ch; }
                if (v[ch].z > m2) { m2 = v[ch].z; i2 = ch; }
                if (v[ch].w > m3) { m3 = v[ch].w; i3 = ch; }
            }
            mom.x = (unsigned)i0 * (((unsigned)i0 << 8) + 1u) + (((unsigned)t0 * (((unsigned)t0 << 8) + 1u)) << 16);
            mom.y = (unsigned)i1 * (((unsigned)i1 << 8) + 1u) + (((unsigned)t1 * (((unsigned)t1 << 8) + 1u)) << 16);
            mom.z = (unsigned)i2 * (((unsigned)i2 << 8) + 1u) + (((unsigned)t2 * (((unsigned)t2 << 8) + 1u)) << 16);
            mom.w = (unsigned)i3 * (((unsigned)i3 << 8) + 1u) + (((unsigned)t3 * (((unsigned)t3 << 8) + 1u)) << 16);
        }
        *(uint4*)&raw[srow][4 + cg] = mom;
        __syncthreads();

        // ---- horizontal 5-sums for the 2 new rows ----
        {
            const uint4 A = *(const uint4*)&raw[srow][cg];       // cols cg-4..cg-1
            const uint4 B = *(const uint4*)&raw[srow][cg + 4];   // cols cg..cg+3
            const uint4 C = *(const uint4*)&raw[srow][cg + 8];   // cols cg+4..cg+7
            unsigned ss = A.z + A.w + B.x + B.y + B.z;
            uint4 o;
            o.x = ss; ss += B.w - A.z;
            o.y = ss; ss += C.x - A.w;
            o.z = ss; ss += C.y - B.x;
            o.w = ss;
            *(uint4*)&hbuf[(2 * s + srow) & 7][cg] = o;
        }
        __syncthreads();

        // ---- vertical sliding window: 2 output rows, 2 cols/thread ----
        if (s >= 2) {
            if (s == 2) {
                #pragma unroll
                for (int d = 0; d < 5; ++d) {
                    const uint2 w = *(const uint2*)&hbuf[d][c0];
                    sa0 += fld_lo(w.x); sb0 += fld_hi(w.x);
                    sa1 += fld_lo(w.y); sb1 += fld_hi(w.y);
                }
            } else {
                const uint2 nw = *(const uint2*)&hbuf[(2 * s) & 7][c0];
                const uint2 ow = *(const uint2*)&hbuf[(2 * s - 5) & 7][c0];
                sa0 += fld_lo(nw.x) - fld_lo(ow.x); sb0 += fld_hi(nw.x) - fld_hi(ow.x);
                sa1 += fld_lo(nw.y) - fld_lo(ow.y); sb1 += fld_hi(nw.y) - fld_hi(ow.y);
            }
            #pragma unroll
            for (int half = 0; half < 2; ++half) {
                {
                    const unsigned q = sb0 * 25u;
                    const int s1c = (int)(sa0 & 0xFFFFu), s1t = (int)(sa0 >> 16);
                    const int np = (int)(q & 0xFFFFu) - s1c * s1c;
                    const int nt = (int)(q >> 16)     - s1t * s1t;
                    acc_i += np + nt;
                    const float p = (float)(np * nt);
                    float sq;
                    asm("sqrt.approx.f32 %0, %1;" : "=f"(sq) : "f"(p));
                    acc_s += sq;
                }
                {
                    const unsigned q = sb1 * 25u;
                    const int s1c = (int)(sa1 & 0xFFFFu), s1t = (int)(sa1 >> 16);
                    const int np = (int)(q & 0xFFFFu) - s1c * s1c;
                    const int nt = (int)(q >> 16)     - s1t * s1t;
                    acc_i += np + nt;
                    const float p = (float)(np * nt);
                    float sq;
                    asm("sqrt.approx.f32 %0, %1;" : "=f"(sq) : "f"(p));
                    acc_s += sq;
                }
                if (half == 0) {   // slide to second output row of this step
                    const uint2 nw = *(const uint2*)&hbuf[(2 * s + 1) & 7][c0];
                    const uint2 ow = *(const uint2*)&hbuf[(2 * s - 4) & 7][c0];
                    sa0 += fld_lo(nw.x) - fld_lo(ow.x); sb0 += fld_hi(nw.x) - fld_hi(ow.x);
                    sa1 += fld_lo(nw.y) - fld_lo(ow.y); sb1 += fld_hi(nw.y) - fld_hi(ow.y);
                }
            }
        }
    }

    // ---- Reduce: warp shuffle -> smem -> one atomic per block ----
    float acc = fmaf(-2.0f, acc_s, (float)acc_i) * (1.0f / (600.0f * NPIX));
    #pragma unroll
    for (int o = 16; o > 0; o >>= 1)
        acc += __shfl_down_sync(0xffffffffu, acc, o);

    if ((tid & 31) == 0) warpsum[tid >> 5] = acc;
    __syncthreads();
    if (tid < 16) {
        float v = warpsum[tid];
        #pragma unroll
        for (int o = 8; o > 0; o >>= 1)
            v += __shfl_down_sync(0xffffu, v, o);
        if (tid == 0) {
            atomicAdd(&g_partial, v);
            __threadfence();
            const int old = atomicAdd(&g_done, 1);
            if (old == NBLOCKS - 1) {
                // Last block: publish and reset for the next graph replay.
                *out = atomicAdd(&g_partial, 0.0f);
                g_partial = 0.0f;
                g_done = 0;
                __threadfence();
            }
        }
    }
}

extern "C" void kernel_launch(void* const* d_in, const int* in_sizes, int n_in,
                              void* d_out, int out_size) {
    const float* pred = (const float*)d_in[0];
    const void*  tgt  = d_in[1];
    float* out = (float*)d_out;

    dim3 grid(NYT, BATCH);
    dcl_onepass<<<grid, 512>>>(pred, tgt, out);
}